// round 17
// baseline (speedup 1.0000x reference)
#include <cuda_runtime.h>
#include <math.h>

#define NMAX 20000
#define CDIM 64
#define NLMD 9
#define NBES 8
#define ZDIM 10

// ---------------- helpers ----------------
__device__ __forceinline__ void red2(float* p, float a, float b) {
  asm volatile("red.global.add.v2.f32 [%0], {%1, %2};" :: "l"(p), "f"(a), "f"(b) : "memory");
}

// ---------------- scratch (device globals; no allocation) ----------------
__device__ float g_msg[NMAX * NLMD * CDIM];   // [N][lm][c]  46.08 MB
__device__ float g_htable[ZDIM * CDIM];
__device__ float g_xout[NMAX * CDIM];
__device__ float g_U3s[NLMD * 45 * 4];        // symmetrized U3: [i][pair][p]
__device__ float g_U2s[45 * 4];               // symmetrized U2: [pair][p]

// ---------------- zero the message buffer ----------------
__global__ void zero_msg_kernel(int n4) {
  int i = blockIdx.x * blockDim.x + threadIdx.x;
  float4* p = reinterpret_cast<float4*>(g_msg);
  if (i < n4) p[i] = make_float4(0.f, 0.f, 0.f, 0.f);
}

// ---------------- species embedding table ----------------
__global__ void htable_kernel(const float* __restrict__ W_embed,
                              const float* __restrict__ W_up) {
  int t = threadIdx.x;
  if (t < ZDIM * CDIM) {
    int z = t >> 6, c = t & 63;
    float acc = 0.f;
    #pragma unroll 8
    for (int k = 0; k < CDIM; k++)
      acc = fmaf(W_embed[z * CDIM + k], W_up[k * CDIM + c], acc);
    g_htable[t] = acc * (1.0f / (3.16227766016838f * 8.0f));  // /(sqrt(10)*sqrt(64))
  }
}

// ---------------- symmetrize U3/U2 over (j,k) ----------------
__global__ void symU_kernel(const float* __restrict__ U3,
                            const float* __restrict__ U2) {
  int t = blockIdx.x * blockDim.x + threadIdx.x;
  if (t >= 9 * 45) return;
  int i = t / 45, pr = t % 45;
  int j = 0, k = 0, acc = 0;
  for (int jj = 0; jj < 9; jj++) {
    int cnt = 9 - jj;
    if (pr < acc + cnt) { j = jj; k = jj + (pr - acc); break; }
    acc += cnt;
  }
  #pragma unroll
  for (int p = 0; p < 4; p++) {
    float v = U3[((i * 9 + j) * 9 + k) * 4 + p];
    if (j != k) v += U3[((i * 9 + k) * 9 + j) * 4 + p];
    g_U3s[(i * 45 + pr) * 4 + p] = v;
  }
  if (i == 0) {
    #pragma unroll
    for (int p = 0; p < 4; p++) {
      float v = U2[(j * 9 + k) * 4 + p];
      if (j != k) v += U2[(k * 9 + j) * 4 + p];
      g_U2s[pr * 4 + p] = v;
    }
  }
}

// ---------------- fused edge kernel (3 blocks/SM, reg-scatter L4) ---------
struct ESmem3 {
  float ACT[128 * 68];     // activation buffer, in-place      (34816 B)
  float WB0[4096];         // weight buffer A                  (16384 B)
  float WB1[4096];         // weight buffer B                  (16384 B)
  float htab[ZDIM * CDIM]; //                                  (2560 B)
  float einfo[128 * 8];    // {rv, zz, ux, uy, uz, -,-,-}      (4096 B)
};                         // total 74240 B -> 3 blocks/SM

// float4-A GEMM over 128 rows, K mult of 4; A stride 68, B stride 64.
// In-place: internal barrier between read-all-A and store (C aliases A).
template <int K, bool ACTF>
__device__ __forceinline__ void gemm128ip(const float* __restrict__ A,
                                          const float* __restrict__ B,
                                          float* __restrict__ Cm, int tid) {
  int rg = tid >> 4, cg = tid & 15;
  float acc[8][4];
  #pragma unroll
  for (int i = 0; i < 8; i++) { acc[i][0] = 0.f; acc[i][1] = 0.f; acc[i][2] = 0.f; acc[i][3] = 0.f; }
  #pragma unroll 1
  for (int k0 = 0; k0 < K; k0 += 4) {
    float4 b0 = *reinterpret_cast<const float4*>(B + (k0 + 0) * 64 + cg * 4);
    float4 b1 = *reinterpret_cast<const float4*>(B + (k0 + 1) * 64 + cg * 4);
    float4 b2 = *reinterpret_cast<const float4*>(B + (k0 + 2) * 64 + cg * 4);
    float4 b3 = *reinterpret_cast<const float4*>(B + (k0 + 3) * 64 + cg * 4);
    #pragma unroll
    for (int i = 0; i < 8; i++) {
      float4 a = *reinterpret_cast<const float4*>(A + (rg + 16 * i) * 68 + k0);
      acc[i][0] = fmaf(a.x, b0.x, acc[i][0]);
      acc[i][1] = fmaf(a.x, b0.y, acc[i][1]);
      acc[i][2] = fmaf(a.x, b0.z, acc[i][2]);
      acc[i][3] = fmaf(a.x, b0.w, acc[i][3]);
      acc[i][0] = fmaf(a.y, b1.x, acc[i][0]);
      acc[i][1] = fmaf(a.y, b1.y, acc[i][1]);
      acc[i][2] = fmaf(a.y, b1.z, acc[i][2]);
      acc[i][3] = fmaf(a.y, b1.w, acc[i][3]);
      acc[i][0] = fmaf(a.z, b2.x, acc[i][0]);
      acc[i][1] = fmaf(a.z, b2.y, acc[i][1]);
      acc[i][2] = fmaf(a.z, b2.z, acc[i][2]);
      acc[i][3] = fmaf(a.z, b2.w, acc[i][3]);
      acc[i][0] = fmaf(a.w, b3.x, acc[i][0]);
      acc[i][1] = fmaf(a.w, b3.y, acc[i][1]);
      acc[i][2] = fmaf(a.w, b3.z, acc[i][2]);
      acc[i][3] = fmaf(a.w, b3.w, acc[i][3]);
    }
  }
  __syncthreads();   // all reads of A complete before overwrite
  #pragma unroll
  for (int i = 0; i < 8; i++) {
    float vv0 = acc[i][0], vv1 = acc[i][1], vv2 = acc[i][2], vv3 = acc[i][3];
    if (ACTF) {
      vv0 = vv0 / (1.0f + __expf(-vv0));
      vv1 = vv1 / (1.0f + __expf(-vv1));
      vv2 = vv2 / (1.0f + __expf(-vv2));
      vv3 = vv3 / (1.0f + __expf(-vv3));
    }
    *reinterpret_cast<float4*>(Cm + (rg + 16 * i) * 68 + cg * 4) =
        make_float4(vv0, vv1, vv2, vv3);
  }
}

// L4 GEMM: accumulators only (no store); rows rg+16i, cols cg*4..+3
__device__ __forceinline__ void gemm128_reg(const float* __restrict__ A,
                                            const float* __restrict__ B,
                                            float acc[8][4], int tid) {
  int rg = tid >> 4, cg = tid & 15;
  #pragma unroll
  for (int i = 0; i < 8; i++) { acc[i][0] = 0.f; acc[i][1] = 0.f; acc[i][2] = 0.f; acc[i][3] = 0.f; }
  #pragma unroll 1
  for (int k0 = 0; k0 < 64; k0 += 4) {
    float4 b0 = *reinterpret_cast<const float4*>(B + (k0 + 0) * 64 + cg * 4);
    float4 b1 = *reinterpret_cast<const float4*>(B + (k0 + 1) * 64 + cg * 4);
    float4 b2 = *reinterpret_cast<const float4*>(B + (k0 + 2) * 64 + cg * 4);
    float4 b3 = *reinterpret_cast<const float4*>(B + (k0 + 3) * 64 + cg * 4);
    #pragma unroll
    for (int i = 0; i < 8; i++) {
      float4 a = *reinterpret_cast<const float4*>(A + (rg + 16 * i) * 68 + k0);
      acc[i][0] = fmaf(a.x, b0.x, acc[i][0]);
      acc[i][1] = fmaf(a.x, b0.y, acc[i][1]);
      acc[i][2] = fmaf(a.x, b0.z, acc[i][2]);
      acc[i][3] = fmaf(a.x, b0.w, acc[i][3]);
      acc[i][0] = fmaf(a.y, b1.x, acc[i][0]);
      acc[i][1] = fmaf(a.y, b1.y, acc[i][1]);
      acc[i][2] = fmaf(a.y, b1.z, acc[i][2]);
      acc[i][3] = fmaf(a.y, b1.w, acc[i][3]);
      acc[i][0] = fmaf(a.z, b2.x, acc[i][0]);
      acc[i][1] = fmaf(a.z, b2.y, acc[i][1]);
      acc[i][2] = fmaf(a.z, b2.z, acc[i][2]);
      acc[i][3] = fmaf(a.z, b2.w, acc[i][3]);
      acc[i][0] = fmaf(a.w, b3.x, acc[i][0]);
      acc[i][1] = fmaf(a.w, b3.y, acc[i][1]);
      acc[i][2] = fmaf(a.w, b3.z, acc[i][2]);
      acc[i][3] = fmaf(a.w, b3.w, acc[i][3]);
    }
  }
}

// register scatter: each thread scatters its own 8 rows x 4 channels.
// Per (row,q): 16 threads x 2 red2 x 8B = 256B contiguous segment.
__device__ __forceinline__ void scatter_reg(float acc[8][4],
                                            const float* __restrict__ htab,
                                            const float* __restrict__ einfo,
                                            int l, int tid) {
  int rg = tid >> 4, cg = tid & 15;
  int lm0 = (l == 0) ? 0 : ((l == 1) ? 1 : 4);
  int cnt = (l == 0) ? 1 : ((l == 1) ? 3 : 5);
  const float c3 = 1.73205080756888f;
  const float c5 = 2.23606797749979f;
  const float c15 = 3.87298334620742f;
  #pragma unroll
  for (int i = 0; i < 8; i++) {
    int e = rg + 16 * i;
    const float* ei = einfo + e * 8;
    int rv = __float_as_int(ei[0]);
    if (rv < 0) continue;
    int zz = __float_as_int(ei[1]);
    float ux = ei[2], uy = ei[3], uz = ei[4];
    float Y[5];
    if (l == 0) {
      Y[0] = 1.0f;
    } else if (l == 1) {
      Y[0] = c3 * ux; Y[1] = c3 * uy; Y[2] = c3 * uz;
    } else {
      Y[0] = c15 * ux * uy;
      Y[1] = c15 * uy * uz;
      Y[2] = 0.5f * c5 * (3.0f * uz * uz - 1.0f);
      Y[3] = c15 * ux * uz;
      Y[4] = 0.5f * c15 * (ux * ux - uy * uy);
    }
    const float* hp = htab + zz * 64 + cg * 4;
    float2 ha = *reinterpret_cast<const float2*>(hp);
    float2 hb = *reinterpret_cast<const float2*>(hp + 2);
    float v0 = acc[i][0] * ha.x;
    float v1 = acc[i][1] * ha.y;
    float v2 = acc[i][2] * hb.x;
    float v3 = acc[i][3] * hb.y;
    float* mp = g_msg + rv * 576 + cg * 4;
    #pragma unroll
    for (int q = 0; q < 5; q++) {
      if (q < cnt) {
        float yv = Y[q];
        float* mq = mp + (lm0 + q) * 64;
        red2(mq,     v0 * yv, v1 * yv);
        red2(mq + 2, v2 * yv, v3 * yv);
      }
    }
  }
}

// copy a 64x64 block (row stride src_stride, col offset c0 in floats,
// c0 MUST be a multiple of 4 for the float4 loads) into dst (stride 64)
__device__ __forceinline__ void copy_w(float* __restrict__ dst,
                                       const float* __restrict__ src,
                                       int src_stride, int c0, int tid) {
  #pragma unroll
  for (int q = 0; q < 4; q++) {
    int f = tid + q * 256, k = f >> 4, c4 = f & 15;
    *reinterpret_cast<float4*>(dst + k * 64 + c4 * 4) =
        *reinterpret_cast<const float4*>(src + k * src_stride + c0 + c4 * 4);
  }
}

extern __shared__ float esmem_raw[];

__global__ void __launch_bounds__(256, 3)
edge_kernel(const float* __restrict__ pos, const int* __restrict__ ai,
            const int* __restrict__ ei,
            const float* __restrict__ w1, const float* __restrict__ w2,
            const float* __restrict__ w3, const float* __restrict__ w4, int E) {
  ESmem3& s = *reinterpret_cast<ESmem3*>(esmem_raw);
  int tid = threadIdx.x;

  // phase 0: stage htab, WB0<-w2, WB1<-w3
  {
    float4* d = (float4*)s.htab;
    const float4* g = (const float4*)g_htable;
    for (int i = tid; i < ZDIM * CDIM / 4; i += 256) d[i] = g[i];
  }
  copy_w(s.WB0, w2, 64, 0, tid);
  copy_w(s.WB1, w3, 64, 0, tid);

  // geometry: EF into ACT (stride 68, cols 0..7), einfo {rv, zz, u}
  if (tid < 128) {
    int eg = blockIdx.x * 128 + tid;
    float* ef = s.ACT + tid * 68;
    float* einf = s.einfo + tid * 8;
    if (eg < E) {
      int sd = ei[eg];
      int rv = ei[E + eg];
      float px = pos[3 * rv + 0] - pos[3 * sd + 0];
      float py = pos[3 * rv + 1] - pos[3 * sd + 1];
      float pz = pos[3 * rv + 2] - pos[3 * sd + 2];
      float r2 = px * px + py * py + pz * pz + 1e-12f;
      float r = sqrtf(r2);
      float inv = 1.0f / r;
      float ux = px * inv, uy = py * inv, uz = pz * inv;
      float u = fminf(r * 0.2f, 1.0f);
      float u2 = u * u, u4 = u2 * u2, u6 = u4 * u2, u7 = u6 * u, u8 = u4 * u4;
      float fc = 1.0f - 28.0f * u6 + 48.0f * u7 - 21.0f * u8;
      float pref = 0.632455532033676f * inv * fc;   // sqrt(2/RMAX)/r * fcut
      float w = 0.628318530717958648f * r;          // pi*r/RMAX
      #pragma unroll
      for (int nb = 1; nb <= 8; nb++) ef[nb - 1] = pref * sinf(w * (float)nb);
      einf[0] = __int_as_float(rv);
      einf[1] = __int_as_float(ai[sd]);
      einf[2] = ux; einf[3] = uy; einf[4] = uz;
    } else {
      #pragma unroll
      for (int q = 0; q < 8; q++) ef[q] = 0.f;
      einf[0] = __int_as_float(-1);
      einf[1] = 0.f; einf[2] = 0.f; einf[3] = 0.f; einf[4] = 0.f;
    }
  }
  __syncthreads();

  // L1: ACT(cols 0..7) @ w1 (global LDG, 8x64, L1-resident) -> ACT in-place
  gemm128ip<8, true>(s.ACT, w1, s.ACT, tid);
  __syncthreads();

  // L2: ACT @ w2(WB0) -> ACT in-place
  gemm128ip<64, true>(s.ACT, s.WB0, s.ACT, tid);
  __syncthreads();                      // WB0 free, ACT(L2) visible

  copy_w(s.WB0, w4, 192, 0, tid);       // WB0 <- w4 cols [0,64)   (overlaps L3)
  // L3: ACT @ w3(WB1) -> ACT in-place
  gemm128ip<64, true>(s.ACT, s.WB1, s.ACT, tid);
  __syncthreads();                      // WB1 free, WB0 chunk visible, ACT(L3) visible

  copy_w(s.WB1, w4, 192, 64, tid);      // WB1 <- w4 cols [64,128)  (overlaps L4c0)
  {
    float acc[8][4];
    // L4 chunk 0: regs -> scatter (warp-local rows, no barrier needed)
    gemm128_reg(s.ACT, s.WB0, acc, tid);
    scatter_reg(acc, s.htab, s.einfo, 0, tid);
    __syncthreads();                    // WB0 free, WB1 visible

    copy_w(s.WB0, w4, 192, 128, tid);   // WB0 <- w4 cols [128,192) (overlaps L4c1)
    // L4 chunk 1
    gemm128_reg(s.ACT, s.WB1, acc, tid);
    scatter_reg(acc, s.htab, s.einfo, 1, tid);
    __syncthreads();                    // WB0 visible

    // L4 chunk 2
    gemm128_reg(s.ACT, s.WB0, acc, tid);
    scatter_reg(acc, s.htab, s.einfo, 2, tid);
  }
}

// ---------------- per-(node, 2-channel) tensor contraction (symmetrized) --
__global__ void __launch_bounds__(256, 3)
contract_kernel(const int* __restrict__ ai, const float* __restrict__ U1,
                const float* __restrict__ Wc3, const float* __restrict__ Wc2,
                const float* __restrict__ Wc1, int N) {
  __shared__ float4 sU3s[9 * 45];  // [i][pair] x p
  __shared__ float4 sU2s[45];
  __shared__ float4 sU1[9];
  __shared__ float sW3[ZDIM * 4 * CDIM];
  __shared__ float sW2[ZDIM * 4 * CDIM];
  __shared__ float sW1[ZDIM * 4 * CDIM];
  int tid = threadIdx.x;
  for (int i = tid; i < 9 * 45; i += 256) sU3s[i] = ((const float4*)g_U3s)[i];
  if (tid < 45) sU2s[tid] = ((const float4*)g_U2s)[tid];
  if (tid >= 64 && tid < 73) sU1[tid - 64] = ((const float4*)U1)[tid - 64];
  for (int i = tid; i < ZDIM * 64; i += 256) {
    ((float4*)sW3)[i] = ((const float4*)Wc3)[i];
    ((float4*)sW2)[i] = ((const float4*)Wc2)[i];
    ((float4*)sW1)[i] = ((const float4*)Wc1)[i];
  }
  __syncthreads();

  int idx = blockIdx.x * 256 + tid;
  if (idx >= N * 32) return;
  int n = idx >> 5, q = idx & 31, c0 = 2 * q;
  int z = ai[n];

  float xa[9], xb[9];
  const float* mrow = g_msg + n * 576 + c0;
  #pragma unroll
  for (int i = 0; i < 9; i++) {
    float2 v = *reinterpret_cast<const float2*>(mrow + i * 64);
    xa[i] = v.x * (1.0f / 16.0f);
    xb[i] = v.y * (1.0f / 16.0f);
  }

  float2 w3p[4], w2p[4], w1p[4];
  #pragma unroll
  for (int p = 0; p < 4; p++) {
    w3p[p] = *reinterpret_cast<const float2*>(sW3 + z * 256 + p * 64 + c0);
    w2p[p] = *reinterpret_cast<const float2*>(sW2 + z * 256 + p * 64 + c0);
    w1p[p] = *reinterpret_cast<const float2*>(sW1 + z * 256 + p * 64 + c0);
  }

  float resA = 0.f, resB = 0.f;
  int pr = 0;
  for (int j = 0; j < 9; j++) {
    float xja = xa[j], xjb = xb[j];
    for (int k = j; k < 9; k++, pr++) {
      float X2a = xja * xa[k];
      float X2b = xjb * xb[k];
      float a0 = 0.f, a1 = 0.f, a2 = 0.f, a3 = 0.f;
      float b0 = 0.f, b1 = 0.f, b2 = 0.f, b3 = 0.f;
      #pragma unroll
      for (int i = 0; i < 9; i++) {
        float4 u3 = sU3s[i * 45 + pr];
        float xia = xa[i], xib = xb[i];
        a0 = fmaf(u3.x, xia, a0); b0 = fmaf(u3.x, xib, b0);
        a1 = fmaf(u3.y, xia, a1); b1 = fmaf(u3.y, xib, b1);
        a2 = fmaf(u3.z, xia, a2); b2 = fmaf(u3.z, xib, b2);
        a3 = fmaf(u3.w, xia, a3); b3 = fmaf(u3.w, xib, b3);
      }
      float4 u2 = sU2s[pr];
      float ta = u2.x * w2p[0].x + u2.y * w2p[1].x + u2.z * w2p[2].x + u2.w * w2p[3].x;
      float tb = u2.x * w2p[0].y + u2.y * w2p[1].y + u2.z * w2p[2].y + u2.w * w2p[3].y;
      ta = fmaf(a0, w3p[0].x, ta); tb = fmaf(b0, w3p[0].y, tb);
      ta = fmaf(a1, w3p[1].x, ta); tb = fmaf(b1, w3p[1].y, tb);
      ta = fmaf(a2, w3p[2].x, ta); tb = fmaf(b2, w3p[2].y, tb);
      ta = fmaf(a3, w3p[3].x, ta); tb = fmaf(b3, w3p[3].y, tb);
      resA = fmaf(ta, X2a, resA);
      resB = fmaf(tb, X2b, resB);
    }
  }
  #pragma unroll
  for (int j = 0; j < 9; j++) {
    float4 u1 = sU1[j];
    float va = u1.x * w1p[0].x + u1.y * w1p[1].x + u1.z * w1p[2].x + u1.w * w1p[3].x;
    float vb = u1.x * w1p[0].y + u1.y * w1p[1].y + u1.z * w1p[2].y + u1.w * w1p[3].y;
    resA = fmaf(va, xa[j], resA);
    resB = fmaf(vb, xb[j], resB);
  }
  *reinterpret_cast<float2*>(g_xout + n * 64 + c0) = make_float2(resA, resB);
}

// ---------------- final output GEMM: out = xout @ W_out / 8 ----------------
__global__ void __launch_bounds__(256)
out_kernel(const float* __restrict__ W_out, float* __restrict__ out, int N) {
  __shared__ float sW[64 * 64];
  __shared__ float sX[64 * 68];
  int tid = threadIdx.x;
  int n0 = blockIdx.x * 64;
  for (int i = tid; i < 1024; i += 256) ((float4*)sW)[i] = ((const float4*)W_out)[i];
  for (int i = tid; i < 64 * 16; i += 256) {
    int r = i >> 4, c4 = i & 15;
    float4 v = make_float4(0.f, 0.f, 0.f, 0.f);
    if (n0 + r < N) v = *reinterpret_cast<const float4*>(g_xout + (n0 + r) * 64 + c4 * 4);
    *reinterpret_cast<float4*>(sX + r * 68 + c4 * 4) = v;
  }
  __syncthreads();
  int rg = tid >> 4, cg = tid & 15;
  float acc[4][4];
  #pragma unroll
  for (int i = 0; i < 4; i++) { acc[i][0] = 0.f; acc[i][1] = 0.f; acc[i][2] = 0.f; acc[i][3] = 0.f; }
  #pragma unroll 4
  for (int k = 0; k < 64; k++) {
    float4 b = *reinterpret_cast<const float4*>(sW + k * 64 + cg * 4);
    #pragma unroll
    for (int i = 0; i < 4; i++) {
      float a = sX[(rg + 16 * i) * 68 + k];
      acc[i][0] = fmaf(a, b.x, acc[i][0]);
      acc[i][1] = fmaf(a, b.y, acc[i][1]);
      acc[i][2] = fmaf(a, b.z, acc[i][2]);
      acc[i][3] = fmaf(a, b.w, acc[i][3]);
    }
  }
  #pragma unroll
  for (int i = 0; i < 4; i++) {
    int n = n0 + rg + 16 * i;
    if (n < N) {
      *reinterpret_cast<float4*>(out + n * 64 + cg * 4) =
          make_float4(acc[i][0] * 0.125f, acc[i][1] * 0.125f,
                      acc[i][2] * 0.125f, acc[i][3] * 0.125f);
    }
  }
}

// ---------------- launch ----------------
extern "C" void kernel_launch(void* const* d_in, const int* in_sizes, int n_in,
                              void* d_out, int out_size) {
  const float* positions = (const float*)d_in[0];
  const int*   ai        = (const int*)d_in[1];
  const int*   ei        = (const int*)d_in[2];
  const float* W_embed   = (const float*)d_in[3];
  const float* W_up      = (const float*)d_in[4];
  const float* w1        = (const float*)d_in[5];
  const float* w2        = (const float*)d_in[6];
  const float* w3        = (const float*)d_in[7];
  const float* w4        = (const float*)d_in[8];
  const float* U3        = (const float*)d_in[9];
  const float* U2        = (const float*)d_in[10];
  const float* U1        = (const float*)d_in[11];
  const float* Wc3       = (const float*)d_in[12];
  const float* Wc2       = (const float*)d_in[13];
  const float* Wc1       = (const float*)d_in[14];
  const float* W_out     = (const float*)d_in[15];
  float* out = (float*)d_out;

  int N = in_sizes[0] / 3;
  int E = in_sizes[2] / 2;

  cudaFuncSetAttribute(edge_kernel, cudaFuncAttributeMaxDynamicSharedMemorySize,
                       (int)sizeof(ESmem3));

  int msg4 = (N * 576) / 4;
  zero_msg_kernel<<<(msg4 + 255) / 256, 256>>>(msg4);
  htable_kernel<<<1, 640>>>(W_embed, W_up);
  symU_kernel<<<2, 256>>>(U3, U2);
  int ntiles = (E + 127) / 128;
  edge_kernel<<<ntiles, 256, sizeof(ESmem3)>>>(positions, ai, ei, w1, w2, w3, w4, E);
  int nc = N * 32;
  contract_kernel<<<(nc + 255) / 256, 256>>>(ai, U1, Wc3, Wc2, Wc1, N);
  out_kernel<<<(N + 63) / 64, 256>>>(W_out, out, N);

  (void)n_in; (void)out_size;
}